// round 1
// baseline (speedup 1.0000x reference)
#include <cuda_runtime.h>
#include <math.h>

// Problem constants (match reference)
#define PW  256          // image width
#define PH  256          // image height
#define TANFOVX 0.5f
#define TANFOVY 0.5f
#define NEARP 0.2f
#define COV_BLUR 0.3f
#define ALPHA_MIN (1.0f/255.0f)
#define ALPHA_MAX 0.99f

#define P_MAX 1024

// Sorted per-gaussian params (global scratch; __device__ arrays are allowed)
__device__ float4 g_p1[P_MAX];  // {px, py, conA, conB}
__device__ float4 g_p2[P_MAX];  // {conC, thr, ln(opa), 0}
__device__ float4 g_col[P_MAX]; // {r, g, b, 0}

// ---------------------------------------------------------------------------
// Preprocess + depth sort. One block, P threads (P <= 1024).
// ---------------------------------------------------------------------------
__global__ void gs_preprocess(const float* __restrict__ means3D,
                              const float* __restrict__ opacities,
                              const float* __restrict__ scales,
                              const float* __restrict__ rotations,
                              const float* __restrict__ colors,
                              const float* __restrict__ viewm,
                              const float* __restrict__ projm,
                              int P)
{
    __shared__ float sdepth[P_MAX];
    int p = threadIdx.x;
    if (p >= P) return;

    float mx = means3D[3*p+0], my = means3D[3*p+1], mz = means3D[3*p+2];

    // opacity -> sigmoid
    float op = 1.0f / (1.0f + expf(-opacities[p]));

    // scales -> exp
    float sx = expf(scales[3*p+0]);
    float sy = expf(scales[3*p+1]);
    float sz = expf(scales[3*p+2]);

    // quaternion -> rotation
    float qr = rotations[4*p+0], qx = rotations[4*p+1];
    float qy = rotations[4*p+2], qz = rotations[4*p+3];
    float qn = sqrtf(qr*qr + qx*qx + qy*qy + qz*qz);
    qn = fmaxf(qn, 1e-12f);
    float inv = 1.0f / qn;
    qr *= inv; qx *= inv; qy *= inv; qz *= inv;

    float R00 = 1.f - 2.f*(qy*qy + qz*qz), R01 = 2.f*(qx*qy - qr*qz), R02 = 2.f*(qx*qz + qr*qy);
    float R10 = 2.f*(qx*qy + qr*qz), R11 = 1.f - 2.f*(qx*qx + qz*qz), R12 = 2.f*(qy*qz - qr*qx);
    float R20 = 2.f*(qx*qz - qr*qy), R21 = 2.f*(qy*qz + qr*qx), R22 = 1.f - 2.f*(qx*qx + qy*qy);

    // L = R * diag(s); cov3D = L L^T  (symmetric, 6 entries)
    float L00 = R00*sx, L01 = R01*sy, L02 = R02*sz;
    float L10 = R10*sx, L11 = R11*sy, L12 = R12*sz;
    float L20 = R20*sx, L21 = R21*sy, L22 = R22*sz;
    float M00 = L00*L00 + L01*L01 + L02*L02;
    float M01 = L00*L10 + L01*L11 + L02*L12;
    float M02 = L00*L20 + L01*L21 + L02*L22;
    float M11 = L10*L10 + L11*L11 + L12*L12;
    float M12 = L10*L20 + L11*L21 + L12*L22;
    float M22 = L20*L20 + L21*L21 + L22*L22;

    // view transform: t = V[:3,:3] @ m + V[:3,3]  (viewm row-major 4x4)
    float tx = viewm[0]*mx + viewm[1]*my + viewm[2] *mz + viewm[3];
    float ty = viewm[4]*mx + viewm[5]*my + viewm[6] *mz + viewm[7];
    float tz = viewm[8]*mx + viewm[9]*my + viewm[10]*mz + viewm[11];

    bool valid = tz > NEARP;
    float tzc = valid ? tz : 1.0f;

    float limx = 1.3f * TANFOVX, limy = 1.3f * TANFOVY;
    float txz = fminf(fmaxf(tx / tzc, -limx), limx) * tzc;
    float tyz = fminf(fmaxf(ty / tzc, -limy), limy) * tzc;

    float fx = (float)PW / (2.0f * TANFOVX);
    float fy = (float)PH / (2.0f * TANFOVY);
    float itz  = 1.0f / tzc;
    float itz2 = itz * itz;
    float J00 = fx * itz,  J02 = -fx * txz * itz2;
    float J11 = fy * itz,  J12 = -fy * tyz * itz2;

    // T2 = J @ V3x3  -> rows u, v
    float u0 = J00*viewm[0] + J02*viewm[8];
    float u1 = J00*viewm[1] + J02*viewm[9];
    float u2 = J00*viewm[2] + J02*viewm[10];
    float v0 = J11*viewm[4] + J12*viewm[8];
    float v1 = J11*viewm[5] + J12*viewm[9];
    float v2 = J11*viewm[6] + J12*viewm[10];

    // M @ u, M @ v
    float Mu0 = M00*u0 + M01*u1 + M02*u2;
    float Mu1 = M01*u0 + M11*u1 + M12*u2;
    float Mu2 = M02*u0 + M12*u1 + M22*u2;
    float Mv0 = M00*v0 + M01*v1 + M02*v2;
    float Mv1 = M01*v0 + M11*v1 + M12*v2;
    float Mv2 = M02*v0 + M12*v1 + M22*v2;

    float c00 = u0*Mu0 + u1*Mu1 + u2*Mu2 + COV_BLUR;
    float c01 = u0*Mv0 + u1*Mv1 + u2*Mv2;
    float c11 = v0*Mv0 + v1*Mv1 + v2*Mv2 + COV_BLUR;

    float det = c00*c11 - c01*c01;
    det = (det == 0.0f) ? 1.0f : det;
    float idet = 1.0f / det;
    float conA = c11 * idet;
    float conB = -c01 * idet;
    float conC = c00 * idet;

    // projection
    float ph0 = projm[0] *mx + projm[1] *my + projm[2] *mz + projm[3];
    float ph1 = projm[4] *mx + projm[5] *my + projm[6] *mz + projm[7];
    float ph3 = projm[12]*mx + projm[13]*my + projm[14]*mz + projm[15];
    float pw  = 1.0f / (ph3 + 1e-7f);
    float pix_x = ((ph0 * pw + 1.0f) * (float)PW - 1.0f) * 0.5f;
    float pix_y = ((ph1 * pw + 1.0f) * (float)PH - 1.0f) * 0.5f;

    float lopa = logf(op);
    float thr  = logf(ALPHA_MIN) - lopa;   // contribute iff power >= thr (and power<=0)
    if (!valid) thr = 1e30f;               // never contributes

    float depth = valid ? tz : INFINITY;
    sdepth[p] = depth;
    __syncthreads();

    // stable rank sort (matches jnp.argsort tie-break)
    int rank = 0;
    for (int j = 0; j < P; j++) {
        float dj = sdepth[j];
        rank += (dj < depth) || (dj == depth && j < p);
    }

    g_p1[rank]  = make_float4(pix_x, pix_y, conA, conB);
    g_p2[rank]  = make_float4(conC, thr, lopa, 0.0f);
    g_col[rank] = make_float4(colors[3*p+0], colors[3*p+1], colors[3*p+2], 0.0f);
}

// ---------------------------------------------------------------------------
// Rasterize: 16x16 pixel blocks, sequential front-to-back blend per pixel.
// ---------------------------------------------------------------------------
__global__ __launch_bounds__(256) void gs_raster(const float* __restrict__ bg,
                                                 float* __restrict__ out,
                                                 int P)
{
    __shared__ float4 s1[P_MAX];
    __shared__ float4 s2[P_MAX];
    __shared__ float4 sc[P_MAX];

    int tid = threadIdx.y * 16 + threadIdx.x;
    for (int i = tid; i < P; i += 256) {
        s1[i] = g_p1[i];
        s2[i] = g_p2[i];
        sc[i] = g_col[i];
    }
    __syncthreads();

    int x = blockIdx.x * 16 + threadIdx.x;
    int y = blockIdx.y * 16 + threadIdx.y;
    float fpx = (float)x;
    float fpy = (float)y;

    float T = 1.0f, cr = 0.0f, cg = 0.0f, cb = 0.0f;

    #pragma unroll 4
    for (int i = 0; i < P; i++) {
        float4 a = s1[i];                 // px, py, A, B
        float dx = a.x - fpx;
        float dy = a.y - fpy;
        float4 b = s2[i];                 // C, thr, lopa
        float power = -0.5f * (a.z * dx * dx + b.x * dy * dy) - a.w * dx * dy;
        if (power > 0.0f || power < b.y) continue;
        float alpha = fminf(ALPHA_MAX, __expf(power + b.z));
        float4 c = sc[i];
        float w = alpha * T;
        cr += w * c.x;
        cg += w * c.y;
        cb += w * c.z;
        T *= (1.0f - alpha);
        if (T < 1e-4f) break;
    }

    float b0 = bg[0], b1 = bg[1], b2 = bg[2];
    int o = (y * PW + x) * 3;
    out[o + 0] = cr + T * b0;
    out[o + 1] = cg + T * b1;
    out[o + 2] = cb + T * b2;
}

// ---------------------------------------------------------------------------
extern "C" void kernel_launch(void* const* d_in, const int* in_sizes, int n_in,
                              void* d_out, int out_size)
{
    const float* means3D   = (const float*)d_in[0];
    const float* opacities = (const float*)d_in[1];
    const float* scales    = (const float*)d_in[2];
    const float* rotations = (const float*)d_in[3];
    const float* colors    = (const float*)d_in[4];
    const float* viewm     = (const float*)d_in[5];
    const float* projm     = (const float*)d_in[6];
    // d_in[7] = campos (unused), d_in[8] = bg
    const float* bg        = (const float*)d_in[8];
    float* out = (float*)d_out;

    int P = in_sizes[0] / 3;
    if (P > P_MAX) P = P_MAX;

    gs_preprocess<<<1, P>>>(means3D, opacities, scales, rotations, colors,
                            viewm, projm, P);
    dim3 grid(PW / 16, PH / 16);
    dim3 block(16, 16);
    gs_raster<<<grid, block>>>(bg, out, P);
}

// round 2
// speedup vs baseline: 2.3862x; 2.3862x over previous
#include <cuda_runtime.h>
#include <math.h>

// Problem constants (match reference)
#define PW  256          // image width
#define PH  256          // image height
#define TANFOVX 0.5f
#define TANFOVY 0.5f
#define NEARP 0.2f
#define COV_BLUR 0.3f
#define ALPHA_MIN (1.0f/255.0f)
#define ALPHA_MAX 0.99f

#define P_MAX 512

// Sorted per-gaussian params (global scratch)
__device__ float4 g_p1[P_MAX];  // {px, py, conA, conB}
__device__ float4 g_p2[P_MAX];  // {conC, thr, ln(opa), 0}
__device__ float4 g_col[P_MAX]; // {r, g, b, 0}
__device__ float4 g_bb[P_MAX];  // {xmin, xmax, ymin, ymax}

// ---------------------------------------------------------------------------
// Preprocess + depth sort. One block, P threads (P <= 512).
// ---------------------------------------------------------------------------
__global__ void gs_preprocess(const float* __restrict__ means3D,
                              const float* __restrict__ opacities,
                              const float* __restrict__ scales,
                              const float* __restrict__ rotations,
                              const float* __restrict__ colors,
                              const float* __restrict__ viewm,
                              const float* __restrict__ projm,
                              int P)
{
    __shared__ float sdepth[P_MAX];
    int p = threadIdx.x;
    if (p >= P) return;

    float mx = means3D[3*p+0], my = means3D[3*p+1], mz = means3D[3*p+2];

    // opacity -> sigmoid
    float op = 1.0f / (1.0f + expf(-opacities[p]));

    // scales -> exp
    float sx = expf(scales[3*p+0]);
    float sy = expf(scales[3*p+1]);
    float sz = expf(scales[3*p+2]);

    // quaternion -> rotation
    float qr = rotations[4*p+0], qx = rotations[4*p+1];
    float qy = rotations[4*p+2], qz = rotations[4*p+3];
    float qn = sqrtf(qr*qr + qx*qx + qy*qy + qz*qz);
    qn = fmaxf(qn, 1e-12f);
    float inv = 1.0f / qn;
    qr *= inv; qx *= inv; qy *= inv; qz *= inv;

    float R00 = 1.f - 2.f*(qy*qy + qz*qz), R01 = 2.f*(qx*qy - qr*qz), R02 = 2.f*(qx*qz + qr*qy);
    float R10 = 2.f*(qx*qy + qr*qz), R11 = 1.f - 2.f*(qx*qx + qz*qz), R12 = 2.f*(qy*qz - qr*qx);
    float R20 = 2.f*(qx*qz - qr*qy), R21 = 2.f*(qy*qz + qr*qx), R22 = 1.f - 2.f*(qx*qx + qy*qy);

    // L = R * diag(s); cov3D = L L^T
    float L00 = R00*sx, L01 = R01*sy, L02 = R02*sz;
    float L10 = R10*sx, L11 = R11*sy, L12 = R12*sz;
    float L20 = R20*sx, L21 = R21*sy, L22 = R22*sz;
    float M00 = L00*L00 + L01*L01 + L02*L02;
    float M01 = L00*L10 + L01*L11 + L02*L12;
    float M02 = L00*L20 + L01*L21 + L02*L22;
    float M11 = L10*L10 + L11*L11 + L12*L12;
    float M12 = L10*L20 + L11*L21 + L12*L22;
    float M22 = L20*L20 + L21*L21 + L22*L22;

    // view transform
    float tx = viewm[0]*mx + viewm[1]*my + viewm[2] *mz + viewm[3];
    float ty = viewm[4]*mx + viewm[5]*my + viewm[6] *mz + viewm[7];
    float tz = viewm[8]*mx + viewm[9]*my + viewm[10]*mz + viewm[11];

    bool valid = tz > NEARP;
    float tzc = valid ? tz : 1.0f;

    float limx = 1.3f * TANFOVX, limy = 1.3f * TANFOVY;
    float txz = fminf(fmaxf(tx / tzc, -limx), limx) * tzc;
    float tyz = fminf(fmaxf(ty / tzc, -limy), limy) * tzc;

    float fx = (float)PW / (2.0f * TANFOVX);
    float fy = (float)PH / (2.0f * TANFOVY);
    float itz  = 1.0f / tzc;
    float itz2 = itz * itz;
    float J00 = fx * itz,  J02 = -fx * txz * itz2;
    float J11 = fy * itz,  J12 = -fy * tyz * itz2;

    // T2 = J @ V3x3 -> rows u, v
    float u0 = J00*viewm[0] + J02*viewm[8];
    float u1 = J00*viewm[1] + J02*viewm[9];
    float u2 = J00*viewm[2] + J02*viewm[10];
    float v0 = J11*viewm[4] + J12*viewm[8];
    float v1 = J11*viewm[5] + J12*viewm[9];
    float v2 = J11*viewm[6] + J12*viewm[10];

    float Mu0 = M00*u0 + M01*u1 + M02*u2;
    float Mu1 = M01*u0 + M11*u1 + M12*u2;
    float Mu2 = M02*u0 + M12*u1 + M22*u2;
    float Mv0 = M00*v0 + M01*v1 + M02*v2;
    float Mv1 = M01*v0 + M11*v1 + M12*v2;
    float Mv2 = M02*v0 + M12*v1 + M22*v2;

    float c00 = u0*Mu0 + u1*Mu1 + u2*Mu2 + COV_BLUR;
    float c01 = u0*Mv0 + u1*Mv1 + u2*Mv2;
    float c11 = v0*Mv0 + v1*Mv1 + v2*Mv2 + COV_BLUR;

    float det = c00*c11 - c01*c01;
    det = (det == 0.0f) ? 1.0f : det;
    float idet = 1.0f / det;
    float conA = c11 * idet;
    float conB = -c01 * idet;
    float conC = c00 * idet;

    // projection -> pixel coords
    float ph0 = projm[0] *mx + projm[1] *my + projm[2] *mz + projm[3];
    float ph1 = projm[4] *mx + projm[5] *my + projm[6] *mz + projm[7];
    float ph3 = projm[12]*mx + projm[13]*my + projm[14]*mz + projm[15];
    float pw  = 1.0f / (ph3 + 1e-7f);
    float pix_x = ((ph0 * pw + 1.0f) * (float)PW - 1.0f) * 0.5f;
    float pix_y = ((ph1 * pw + 1.0f) * (float)PH - 1.0f) * 0.5f;

    float lopa = logf(op);
    float thr  = logf(ALPHA_MIN) - lopa;  // contribute iff thr <= power <= 0

    // footprint bbox: ellipse {power >= thr}. Since conic = cov^-1,
    // half-extents are sqrt(2*tau*c00), sqrt(2*tau*c11) with tau = -thr.
    float4 bb;
    if (!valid || thr > 0.0f) {
        thr = 1e30f;
        bb = make_float4(1e30f, -1e30f, 1e30f, -1e30f);   // empty
    } else {
        float tau = -thr;
        float ex = sqrtf(2.0f * tau * c00);
        float ey = sqrtf(2.0f * tau * c11);
        bb = make_float4(pix_x - ex, pix_x + ex, pix_y - ey, pix_y + ey);
    }

    float depth = valid ? tz : INFINITY;
    sdepth[p] = depth;
    __syncthreads();

    // stable rank sort (matches jnp.argsort tie-break)
    int rank = 0;
    for (int j = 0; j < P; j++) {
        float dj = sdepth[j];
        rank += (dj < depth) || (dj == depth && j < p);
    }

    g_p1[rank]  = make_float4(pix_x, pix_y, conA, conB);
    g_p2[rank]  = make_float4(conC, thr, lopa, 0.0f);
    g_col[rank] = make_float4(colors[3*p+0], colors[3*p+1], colors[3*p+2], 0.0f);
    g_bb[rank]  = bb;
}

// ---------------------------------------------------------------------------
// Rasterize: 16x16 pixel tiles. Phase 1: order-preserving compaction of
// gaussians intersecting the tile. Phase 2: per-pixel front-to-back blend
// over survivors only.
// ---------------------------------------------------------------------------
__global__ __launch_bounds__(256) void gs_raster(const float* __restrict__ bg,
                                                 float* __restrict__ out,
                                                 int P)
{
    __shared__ float4 s1[P_MAX];
    __shared__ float4 s2[P_MAX];
    __shared__ float4 sc[P_MAX];
    __shared__ int warpcnt[8];
    __shared__ int warpoff[8];
    __shared__ int s_total;

    int tid  = threadIdx.y * 16 + threadIdx.x;
    int wid  = tid >> 5;
    int lane = tid & 31;

    float tx0 = (float)(blockIdx.x * 16);
    float tx1 = tx0 + 15.0f;
    float ty0 = (float)(blockIdx.y * 16);
    float ty1 = ty0 + 15.0f;

    // ---- Phase 1: build compacted, depth-ordered survivor list ----
    int count = 0;
    for (int base = 0; base < P; base += 256) {
        int i = base + tid;
        bool pred = false;
        if (i < P) {
            float4 bb = g_bb[i];
            pred = (bb.x <= tx1) && (bb.y >= tx0) && (bb.z <= ty1) && (bb.w >= ty0);
        }
        unsigned m = __ballot_sync(0xffffffffu, pred);
        if (lane == 0) warpcnt[wid] = __popc(m);
        __syncthreads();
        if (tid == 0) {
            int acc = count;
            #pragma unroll
            for (int w = 0; w < 8; w++) { warpoff[w] = acc; acc += warpcnt[w]; }
            s_total = acc;
        }
        __syncthreads();
        if (pred) {
            int pos = warpoff[wid] + __popc(m & ((1u << lane) - 1u));
            s1[pos] = g_p1[i];
            s2[pos] = g_p2[i];
            sc[pos] = g_col[i];
        }
        __syncthreads();
        count = s_total;
    }

    // ---- Phase 2: per-pixel blend over survivors ----
    float fpx = tx0 + (float)threadIdx.x;
    float fpy = ty0 + (float)threadIdx.y;

    float T = 1.0f, cr = 0.0f, cg = 0.0f, cb = 0.0f;

    #pragma unroll 4
    for (int i = 0; i < count; i++) {
        float4 a = s1[i];                 // px, py, A, B
        float dx = a.x - fpx;
        float dy = a.y - fpy;
        float4 b = s2[i];                 // C, thr, lopa
        float power = -0.5f * (a.z * dx * dx + b.x * dy * dy) - a.w * dx * dy;
        if (power > 0.0f || power < b.y) continue;
        float alpha = fminf(ALPHA_MAX, __expf(power + b.z));
        float4 c = sc[i];
        float w = alpha * T;
        cr += w * c.x;
        cg += w * c.y;
        cb += w * c.z;
        T *= (1.0f - alpha);
        if (T < 1e-4f) break;
    }

    float b0 = bg[0], b1 = bg[1], b2 = bg[2];
    int x = blockIdx.x * 16 + threadIdx.x;
    int y = blockIdx.y * 16 + threadIdx.y;
    int o = (y * PW + x) * 3;
    out[o + 0] = cr + T * b0;
    out[o + 1] = cg + T * b1;
    out[o + 2] = cb + T * b2;
}

// ---------------------------------------------------------------------------
extern "C" void kernel_launch(void* const* d_in, const int* in_sizes, int n_in,
                              void* d_out, int out_size)
{
    const float* means3D   = (const float*)d_in[0];
    const float* opacities = (const float*)d_in[1];
    const float* scales    = (const float*)d_in[2];
    const float* rotations = (const float*)d_in[3];
    const float* colors    = (const float*)d_in[4];
    const float* viewm     = (const float*)d_in[5];
    const float* projm     = (const float*)d_in[6];
    // d_in[7] = campos (unused), d_in[8] = bg
    const float* bg        = (const float*)d_in[8];
    float* out = (float*)d_out;

    int P = in_sizes[0] / 3;
    if (P > P_MAX) P = P_MAX;

    gs_preprocess<<<1, P>>>(means3D, opacities, scales, rotations, colors,
                            viewm, projm, P);
    dim3 grid(PW / 16, PH / 16);
    dim3 block(16, 16);
    gs_raster<<<grid, block>>>(bg, out, P);
}

// round 4
// speedup vs baseline: 3.3723x; 1.4133x over previous
#include <cuda_runtime.h>
#include <math.h>

// Problem constants (match reference)
#define PW  256          // image width
#define PH  256          // image height
#define TANFOVX 0.5f
#define TANFOVY 0.5f
#define NEARP 0.2f
#define COV_BLUR 0.3f
#define ALPHA_MIN (1.0f/255.0f)
#define ALPHA_MAX 0.99f

#define P_MAX 512
#define PRE_BLOCKS 8
#define PRE_THREADS 64

// Sorted per-gaussian params (global scratch)
__device__ float4 g_p1[P_MAX];  // {px, py, conA, conB}
__device__ float4 g_p2[P_MAX];  // {conC, thr, lopa, 0}
__device__ float4 g_col[P_MAX]; // {r, g, b, 0}
__device__ float4 g_bb[P_MAX];  // {xmin, xmax, ymin, ymax}

// ---------------------------------------------------------------------------
// Preprocess + depth sort. PRE_BLOCKS blocks; each handles a slice of
// gaussians but redundantly computes all P depths (cheap) for the rank sort.
// ---------------------------------------------------------------------------
__global__ __launch_bounds__(PRE_THREADS)
void gs_preprocess(const float* __restrict__ means3D,
                   const float* __restrict__ opacities,
                   const float* __restrict__ scales,
                   const float* __restrict__ rotations,
                   const float* __restrict__ colors,
                   const float* __restrict__ viewm,
                   const float* __restrict__ projm,
                   int P)
{
    __shared__ float sdepth[P_MAX];
    int tid = threadIdx.x;

    // view row 2 (for depth)
    float v8 = viewm[8], v9 = viewm[9], v10 = viewm[10], v11 = viewm[11];

    // all threads: compute every gaussian's depth into shared
    for (int i = tid; i < P; i += PRE_THREADS) {
        float mx = means3D[3*i+0], my = means3D[3*i+1], mz = means3D[3*i+2];
        float tzi = v8*mx + v9*my + v10*mz + v11;
        sdepth[i] = (tzi > NEARP) ? tzi : INFINITY;
    }
    __syncthreads();

    int p = blockIdx.x * PRE_THREADS + tid;
    if (p >= P) return;

    float mx = means3D[3*p+0], my = means3D[3*p+1], mz = means3D[3*p+2];

    // opacity -> sigmoid
    float op = 1.0f / (1.0f + expf(-opacities[p]));

    // scales -> exp
    float sx = expf(scales[3*p+0]);
    float sy = expf(scales[3*p+1]);
    float sz = expf(scales[3*p+2]);

    // quaternion -> rotation
    float qr = rotations[4*p+0], qx = rotations[4*p+1];
    float qy = rotations[4*p+2], qz = rotations[4*p+3];
    float qn = sqrtf(qr*qr + qx*qx + qy*qy + qz*qz);
    qn = fmaxf(qn, 1e-12f);
    float inv = 1.0f / qn;
    qr *= inv; qx *= inv; qy *= inv; qz *= inv;

    float R00 = 1.f - 2.f*(qy*qy + qz*qz), R01 = 2.f*(qx*qy - qr*qz), R02 = 2.f*(qx*qz + qr*qy);
    float R10 = 2.f*(qx*qy + qr*qz), R11 = 1.f - 2.f*(qx*qx + qz*qz), R12 = 2.f*(qy*qz - qr*qx);
    float R20 = 2.f*(qx*qz - qr*qy), R21 = 2.f*(qy*qz + qr*qx), R22 = 1.f - 2.f*(qx*qx + qy*qy);

    // L = R * diag(s); cov3D = L L^T
    float L00 = R00*sx, L01 = R01*sy, L02 = R02*sz;
    float L10 = R10*sx, L11 = R11*sy, L12 = R12*sz;
    float L20 = R20*sx, L21 = R21*sy, L22 = R22*sz;
    float M00 = L00*L00 + L01*L01 + L02*L02;
    float M01 = L00*L10 + L01*L11 + L02*L12;
    float M02 = L00*L20 + L01*L21 + L02*L22;
    float M11 = L10*L10 + L11*L11 + L12*L12;
    float M12 = L10*L20 + L11*L21 + L12*L22;
    float M22 = L20*L20 + L21*L21 + L22*L22;

    // view transform
    float tx = viewm[0]*mx + viewm[1]*my + viewm[2] *mz + viewm[3];
    float ty = viewm[4]*mx + viewm[5]*my + viewm[6] *mz + viewm[7];
    float tz = v8*mx + v9*my + v10*mz + v11;

    bool valid = tz > NEARP;
    float tzc = valid ? tz : 1.0f;

    float limx = 1.3f * TANFOVX, limy = 1.3f * TANFOVY;
    float txz = fminf(fmaxf(tx / tzc, -limx), limx) * tzc;
    float tyz = fminf(fmaxf(ty / tzc, -limy), limy) * tzc;

    float fx = (float)PW / (2.0f * TANFOVX);
    float fy = (float)PH / (2.0f * TANFOVY);
    float itz  = 1.0f / tzc;
    float itz2 = itz * itz;
    float J00 = fx * itz,  J02 = -fx * txz * itz2;
    float J11 = fy * itz,  J12 = -fy * tyz * itz2;

    // T2 = J @ V3x3 -> rows u, v
    float u0 = J00*viewm[0] + J02*viewm[8];
    float u1 = J00*viewm[1] + J02*viewm[9];
    float u2 = J00*viewm[2] + J02*viewm[10];
    float v0 = J11*viewm[4] + J12*viewm[8];
    float v1 = J11*viewm[5] + J12*viewm[9];
    float v2 = J11*viewm[6] + J12*viewm[10];

    float Mu0 = M00*u0 + M01*u1 + M02*u2;
    float Mu1 = M01*u0 + M11*u1 + M12*u2;
    float Mu2 = M02*u0 + M12*u1 + M22*u2;
    float Mv0 = M00*v0 + M01*v1 + M02*v2;
    float Mv1 = M01*v0 + M11*v1 + M12*v2;
    float Mv2 = M02*v0 + M12*v1 + M22*v2;

    float c00 = u0*Mu0 + u1*Mu1 + u2*Mu2 + COV_BLUR;
    float c01 = u0*Mv0 + u1*Mv1 + u2*Mv2;
    float c11 = v0*Mv0 + v1*Mv1 + v2*Mv2 + COV_BLUR;

    float det = c00*c11 - c01*c01;
    det = (det == 0.0f) ? 1.0f : det;
    float idet = 1.0f / det;
    float conA = c11 * idet;
    float conB = -c01 * idet;
    float conC = c00 * idet;

    // projection -> pixel coords
    float ph0 = projm[0] *mx + projm[1] *my + projm[2] *mz + projm[3];
    float ph1 = projm[4] *mx + projm[5] *my + projm[6] *mz + projm[7];
    float ph3 = projm[12]*mx + projm[13]*my + projm[14]*mz + projm[15];
    float pw  = 1.0f / (ph3 + 1e-7f);
    float pix_x = ((ph0 * pw + 1.0f) * (float)PW - 1.0f) * 0.5f;
    float pix_y = ((ph1 * pw + 1.0f) * (float)PH - 1.0f) * 0.5f;

    float lopa = logf(op);
    float thr  = logf(ALPHA_MIN) - lopa;  // contribute iff thr <= power <= 0

    // footprint bbox: ellipse {power >= thr}; conic = cov^-1 =>
    // half-extents sqrt(2*tau*c00), sqrt(2*tau*c11), tau = -thr.
    float4 bb;
    if (!valid || thr > 0.0f) {
        thr = 1e30f;
        bb = make_float4(1e30f, -1e30f, 1e30f, -1e30f);   // empty
    } else {
        float tau = -thr;
        float ex = sqrtf(2.0f * tau * c00);
        float ey = sqrtf(2.0f * tau * c11);
        bb = make_float4(pix_x - ex, pix_x + ex, pix_y - ey, pix_y + ey);
    }

    float depth = valid ? tz : INFINITY;

    // stable rank sort (matches jnp.argsort tie-break)
    int rank = 0;
    #pragma unroll 8
    for (int j = 0; j < P; j++) {
        float dj = sdepth[j];
        rank += (dj < depth) || (dj == depth && j < p);
    }

    g_p1[rank]  = make_float4(pix_x, pix_y, conA, conB);
    g_p2[rank]  = make_float4(conC, thr, lopa, 0.0f);
    g_col[rank] = make_float4(colors[3*p+0], colors[3*p+1], colors[3*p+2], 0.0f);
    g_bb[rank]  = bb;
}

// ---------------------------------------------------------------------------
// Rasterize: 16x16 pixel tiles. Phase 1: order-preserving compaction of
// gaussians intersecting the tile. Phase 2: per-pixel front-to-back blend
// over survivors only.
// ---------------------------------------------------------------------------
__global__ __launch_bounds__(256) void gs_raster(const float* __restrict__ bg,
                                                 float* __restrict__ out,
                                                 int P)
{
    __shared__ float4 s1[P_MAX];
    __shared__ float4 s2[P_MAX];
    __shared__ float4 sc[P_MAX];
    __shared__ int warpcnt[8];
    __shared__ int warpoff[8];
    __shared__ int s_total;

    int tid  = threadIdx.y * 16 + threadIdx.x;
    int wid  = tid >> 5;
    int lane = tid & 31;

    float tx0 = (float)(blockIdx.x * 16);
    float tx1 = tx0 + 15.0f;
    float ty0 = (float)(blockIdx.y * 16);
    float ty1 = ty0 + 15.0f;

    // ---- Phase 1: build compacted, depth-ordered survivor list ----
    int count = 0;
    for (int base = 0; base < P; base += 256) {
        int i = base + tid;
        bool pred = false;
        if (i < P) {
            float4 bb = g_bb[i];
            pred = (bb.x <= tx1) && (bb.y >= tx0) && (bb.z <= ty1) && (bb.w >= ty0);
        }
        unsigned m = __ballot_sync(0xffffffffu, pred);
        if (lane == 0) warpcnt[wid] = __popc(m);
        __syncthreads();
        if (tid == 0) {
            int acc = count;
            #pragma unroll
            for (int w = 0; w < 8; w++) { warpoff[w] = acc; acc += warpcnt[w]; }
            s_total = acc;
        }
        __syncthreads();
        if (pred) {
            int pos = warpoff[wid] + __popc(m & ((1u << lane) - 1u));
            s1[pos] = g_p1[i];
            s2[pos] = g_p2[i];
            sc[pos] = g_col[i];
        }
        __syncthreads();
        count = s_total;
    }

    // ---- Phase 2: per-pixel blend over survivors ----
    float fpx = tx0 + (float)threadIdx.x;
    float fpy = ty0 + (float)threadIdx.y;

    float T = 1.0f, cr = 0.0f, cg = 0.0f, cb = 0.0f;

    #pragma unroll 4
    for (int i = 0; i < count; i++) {
        float4 a = s1[i];                 // px, py, A, B
        float dx = a.x - fpx;
        float dy = a.y - fpy;
        float4 b = s2[i];                 // C, thr, lopa
        float power = -0.5f * (a.z * dx * dx + b.x * dy * dy) - a.w * dx * dy;
        if (power > 0.0f || power < b.y) continue;
        float alpha = fminf(ALPHA_MAX, __expf(power + b.z));
        float4 c = sc[i];
        float w = alpha * T;
        cr += w * c.x;
        cg += w * c.y;
        cb += w * c.z;
        T *= (1.0f - alpha);
        if (T < 1e-4f) break;
    }

    float b0 = bg[0], b1 = bg[1], b2 = bg[2];
    int x = blockIdx.x * 16 + threadIdx.x;
    int y = blockIdx.y * 16 + threadIdx.y;
    int o = (y * PW + x) * 3;
    out[o + 0] = cr + T * b0;
    out[o + 1] = cg + T * b1;
    out[o + 2] = cb + T * b2;
}

// ---------------------------------------------------------------------------
extern "C" void kernel_launch(void* const* d_in, const int* in_sizes, int n_in,
                              void* d_out, int out_size)
{
    const float* means3D   = (const float*)d_in[0];
    const float* opacities = (const float*)d_in[1];
    const float* scales    = (const float*)d_in[2];
    const float* rotations = (const float*)d_in[3];
    const float* colors    = (const float*)d_in[4];
    const float* viewm     = (const float*)d_in[5];
    const float* projm     = (const float*)d_in[6];
    // d_in[7] = campos (unused), d_in[8] = bg
    const float* bg        = (const float*)d_in[8];
    float* out = (float*)d_out;

    int P = in_sizes[0] / 3;
    if (P > P_MAX) P = P_MAX;

    gs_preprocess<<<PRE_BLOCKS, PRE_THREADS>>>(means3D, opacities, scales,
                                               rotations, colors, viewm, projm, P);
    dim3 grid(PW / 16, PH / 16);
    dim3 block(16, 16);
    gs_raster<<<grid, block>>>(bg, out, P);
}

// round 5
// speedup vs baseline: 5.2584x; 1.5593x over previous
#include <cuda_runtime.h>
#include <math.h>

// Problem constants (match reference)
#define PW  256          // image width
#define PH  256          // image height
#define TANFOVX 0.5f
#define TANFOVY 0.5f
#define NEARP 0.2f
#define COV_BLUR 0.3f
#define ALPHA_MIN (1.0f/255.0f)
#define ALPHA_MAX 0.99f

#define P_MAX 512
#define TILE_W 32
#define TILE_H 16
#define NTHREADS 512     // == P_MAX: one gaussian per thread, one pixel per thread
#define NWARPS (NTHREADS/32)

// ---------------------------------------------------------------------------
// Fused kernel: each block (one 32x16 pixel tile) independently preprocesses
// all P gaussians (1 per thread), compacts the tile's survivors in original
// index order, rank-sorts survivors by depth (exactly reproducing stable
// argsort restricted to survivors — excluded gaussians have alpha=0 and do
// not affect compositing), then blends front-to-back per pixel.
// ---------------------------------------------------------------------------
__global__ __launch_bounds__(NTHREADS)
void gs_fused(const float* __restrict__ means3D,
              const float* __restrict__ opacities,
              const float* __restrict__ scales,
              const float* __restrict__ rotations,
              const float* __restrict__ colors,
              const float* __restrict__ viewm,
              const float* __restrict__ projm,
              const float* __restrict__ bg,
              float* __restrict__ out,
              int P)
{
    __shared__ float  sdep[P_MAX];
    __shared__ float4 s1[P_MAX];   // {px, py, conA, conB}
    __shared__ float4 s2[P_MAX];   // {conC, thr, lopa, 0}
    __shared__ float4 sc[P_MAX];   // {r, g, b, 0}
    __shared__ int warpcnt[NWARPS];
    __shared__ int warpoff[NWARPS];
    __shared__ int s_count;

    int tid  = threadIdx.x;
    int wid  = tid >> 5;
    int lane = tid & 31;

    float tx0 = (float)(blockIdx.x * TILE_W);
    float tx1 = tx0 + (float)(TILE_W - 1);
    float ty0 = (float)(blockIdx.y * TILE_H);
    float ty1 = ty0 + (float)(TILE_H - 1);

    // ---- Preprocess my gaussian (p == tid) ----
    bool  pred  = false;
    float pix_x = 0.f, pix_y = 0.f, conA = 0.f, conB = 0.f, conC = 0.f;
    float thr = 0.f, lopa = 0.f, depth = 0.f;
    float4 col = make_float4(0.f, 0.f, 0.f, 0.f);

    int p = tid;
    if (p < P) {
        float mx = means3D[3*p+0], my = means3D[3*p+1], mz = means3D[3*p+2];

        // opacity -> sigmoid (log-space: lopa = -log1p(exp(-o)))
        float op = 1.0f / (1.0f + __expf(-opacities[p]));

        float sx = __expf(scales[3*p+0]);
        float sy = __expf(scales[3*p+1]);
        float sz = __expf(scales[3*p+2]);

        float qr = rotations[4*p+0], qx = rotations[4*p+1];
        float qy = rotations[4*p+2], qz = rotations[4*p+3];
        float qn = sqrtf(qr*qr + qx*qx + qy*qy + qz*qz);
        qn = fmaxf(qn, 1e-12f);
        float inv = 1.0f / qn;
        qr *= inv; qx *= inv; qy *= inv; qz *= inv;

        float R00 = 1.f - 2.f*(qy*qy + qz*qz), R01 = 2.f*(qx*qy - qr*qz), R02 = 2.f*(qx*qz + qr*qy);
        float R10 = 2.f*(qx*qy + qr*qz), R11 = 1.f - 2.f*(qx*qx + qz*qz), R12 = 2.f*(qy*qz - qr*qx);
        float R20 = 2.f*(qx*qz - qr*qy), R21 = 2.f*(qy*qz + qr*qx), R22 = 1.f - 2.f*(qx*qx + qy*qy);

        float L00 = R00*sx, L01 = R01*sy, L02 = R02*sz;
        float L10 = R10*sx, L11 = R11*sy, L12 = R12*sz;
        float L20 = R20*sx, L21 = R21*sy, L22 = R22*sz;
        float M00 = L00*L00 + L01*L01 + L02*L02;
        float M01 = L00*L10 + L01*L11 + L02*L12;
        float M02 = L00*L20 + L01*L21 + L02*L22;
        float M11 = L10*L10 + L11*L11 + L12*L12;
        float M12 = L10*L20 + L11*L21 + L12*L22;
        float M22 = L20*L20 + L21*L21 + L22*L22;

        float tx = viewm[0]*mx + viewm[1]*my + viewm[2] *mz + viewm[3];
        float ty = viewm[4]*mx + viewm[5]*my + viewm[6] *mz + viewm[7];
        float tz = viewm[8]*mx + viewm[9]*my + viewm[10]*mz + viewm[11];

        bool valid = tz > NEARP;
        float tzc = valid ? tz : 1.0f;

        float limx = 1.3f * TANFOVX, limy = 1.3f * TANFOVY;
        float txz = fminf(fmaxf(tx / tzc, -limx), limx) * tzc;
        float tyz = fminf(fmaxf(ty / tzc, -limy), limy) * tzc;

        float fx = (float)PW / (2.0f * TANFOVX);
        float fy = (float)PH / (2.0f * TANFOVY);
        float itz  = 1.0f / tzc;
        float itz2 = itz * itz;
        float J00 = fx * itz,  J02 = -fx * txz * itz2;
        float J11 = fy * itz,  J12 = -fy * tyz * itz2;

        float u0 = J00*viewm[0] + J02*viewm[8];
        float u1 = J00*viewm[1] + J02*viewm[9];
        float u2 = J00*viewm[2] + J02*viewm[10];
        float v0 = J11*viewm[4] + J12*viewm[8];
        float v1 = J11*viewm[5] + J12*viewm[9];
        float v2 = J11*viewm[6] + J12*viewm[10];

        float Mu0 = M00*u0 + M01*u1 + M02*u2;
        float Mu1 = M01*u0 + M11*u1 + M12*u2;
        float Mu2 = M02*u0 + M12*u1 + M22*u2;
        float Mv0 = M00*v0 + M01*v1 + M02*v2;
        float Mv1 = M01*v0 + M11*v1 + M12*v2;
        float Mv2 = M02*v0 + M12*v1 + M22*v2;

        float c00 = u0*Mu0 + u1*Mu1 + u2*Mu2 + COV_BLUR;
        float c01 = u0*Mv0 + u1*Mv1 + u2*Mv2;
        float c11 = v0*Mv0 + v1*Mv1 + v2*Mv2 + COV_BLUR;

        float det = c00*c11 - c01*c01;
        det = (det == 0.0f) ? 1.0f : det;
        float idet = 1.0f / det;
        conA = c11 * idet;
        conB = -c01 * idet;
        conC = c00 * idet;

        float ph0 = projm[0] *mx + projm[1] *my + projm[2] *mz + projm[3];
        float ph1 = projm[4] *mx + projm[5] *my + projm[6] *mz + projm[7];
        float ph3 = projm[12]*mx + projm[13]*my + projm[14]*mz + projm[15];
        float pw  = 1.0f / (ph3 + 1e-7f);
        pix_x = ((ph0 * pw + 1.0f) * (float)PW - 1.0f) * 0.5f;
        pix_y = ((ph1 * pw + 1.0f) * (float)PH - 1.0f) * 0.5f;

        lopa = __logf(op);
        thr  = __logf(ALPHA_MIN) - lopa;   // contribute iff thr <= power <= 0
        depth = tz;

        if (valid && thr <= 0.0f) {
            float tau = -thr;
            float ex = sqrtf(2.0f * tau * c00);
            float ey = sqrtf(2.0f * tau * c11);
            pred = (pix_x - ex <= tx1) && (pix_x + ex >= tx0) &&
                   (pix_y - ey <= ty1) && (pix_y + ey >= ty0);
        }
        if (pred) {
            col = make_float4(colors[3*p+0], colors[3*p+1], colors[3*p+2], 0.0f);
        }
    }

    // ---- Compact survivors (original index order preserved) ----
    unsigned m = __ballot_sync(0xffffffffu, pred);
    if (lane == 0) warpcnt[wid] = __popc(m);
    __syncthreads();
    if (tid == 0) {
        int acc = 0;
        #pragma unroll
        for (int w = 0; w < NWARPS; w++) { warpoff[w] = acc; acc += warpcnt[w]; }
        s_count = acc;
    }
    __syncthreads();

    int pos = 0;
    if (pred) {
        pos = warpoff[wid] + __popc(m & ((1u << lane) - 1u));
        sdep[pos] = depth;
    }
    __syncthreads();
    int count = s_count;

    // ---- Rank-sort survivors by depth (stable via compact index) ----
    if (pred) {
        int rank = 0;
        for (int j = 0; j < count; j++) {
            float dj = sdep[j];
            rank += (dj < depth) || (dj == depth && j < pos);
        }
        s1[rank] = make_float4(pix_x, pix_y, conA, conB);
        s2[rank] = make_float4(conC, thr, lopa, 0.0f);
        sc[rank] = col;
    }
    __syncthreads();

    // ---- Per-pixel front-to-back blend over sorted survivors ----
    int lx = tid & (TILE_W - 1);
    int ly = tid / TILE_W;
    float fpx = tx0 + (float)lx;
    float fpy = ty0 + (float)ly;

    float T = 1.0f, cr = 0.0f, cg = 0.0f, cb = 0.0f;

    #pragma unroll 4
    for (int i = 0; i < count; i++) {
        float4 a = s1[i];                 // px, py, A, B
        float dx = a.x - fpx;
        float dy = a.y - fpy;
        float4 b = s2[i];                 // C, thr, lopa
        float power = -0.5f * (a.z * dx * dx + b.x * dy * dy) - a.w * dx * dy;
        if (power > 0.0f || power < b.y) continue;
        float alpha = fminf(ALPHA_MAX, __expf(power + b.z));
        float4 c = sc[i];
        float w = alpha * T;
        cr += w * c.x;
        cg += w * c.y;
        cb += w * c.z;
        T *= (1.0f - alpha);
        if (T < 1e-4f) break;
    }

    float b0 = bg[0], b1 = bg[1], b2 = bg[2];
    int x = blockIdx.x * TILE_W + lx;
    int y = blockIdx.y * TILE_H + ly;
    int o = (y * PW + x) * 3;
    out[o + 0] = cr + T * b0;
    out[o + 1] = cg + T * b1;
    out[o + 2] = cb + T * b2;
}

// ---------------------------------------------------------------------------
extern "C" void kernel_launch(void* const* d_in, const int* in_sizes, int n_in,
                              void* d_out, int out_size)
{
    const float* means3D   = (const float*)d_in[0];
    const float* opacities = (const float*)d_in[1];
    const float* scales    = (const float*)d_in[2];
    const float* rotations = (const float*)d_in[3];
    const float* colors    = (const float*)d_in[4];
    const float* viewm     = (const float*)d_in[5];
    const float* projm     = (const float*)d_in[6];
    // d_in[7] = campos (unused), d_in[8] = bg
    const float* bg        = (const float*)d_in[8];
    float* out = (float*)d_out;

    int P = in_sizes[0] / 3;
    if (P > P_MAX) P = P_MAX;

    dim3 grid(PW / TILE_W, PH / TILE_H);   // 8 x 16 = 128 blocks
    gs_fused<<<grid, NTHREADS>>>(means3D, opacities, scales, rotations, colors,
                                 viewm, projm, bg, out, P);
}

// round 6
// speedup vs baseline: 5.4747x; 1.0411x over previous
#include <cuda_runtime.h>
#include <math.h>

// Problem constants (match reference)
#define PW  256          // image width
#define PH  256          // image height
#define TANFOVX 0.5f
#define TANFOVY 0.5f
#define NEARP 0.2f
#define COV_BLUR 0.3f
#define ALPHA_MIN (1.0f/255.0f)
#define ALPHA_MAX 0.99f

#define P_MAX 512
#define TILE_W 16
#define TILE_H 16
#define NPIX (TILE_W*TILE_H)     // 256 pixels per tile
#define NTHREADS 512             // 2 threads per pixel (front/back list halves)
#define NWARPS (NTHREADS/32)

// ---------------------------------------------------------------------------
// Fused kernel: each block (one 16x16 tile) preprocesses all P gaussians
// (1/thread), compacts + rank-sorts this tile's survivors by depth, then
// composites. Compositing is split: threads [0,256) blend the front half of
// the sorted list, threads [256,512) the back half; the halves combine via
// the associativity of the "over" operator:
//     c_total = c_front + T_front * c_back,   T_total = T_front * T_back.
// ---------------------------------------------------------------------------
__global__ __launch_bounds__(NTHREADS, 2)
void gs_fused(const float* __restrict__ means3D,
              const float* __restrict__ opacities,
              const float* __restrict__ scales,
              const float* __restrict__ rotations,
              const float* __restrict__ colors,
              const float* __restrict__ viewm,
              const float* __restrict__ projm,
              const float* __restrict__ bg,
              float* __restrict__ out,
              int P)
{
    __shared__ float  sdep[P_MAX];
    __shared__ float4 s1[P_MAX];   // {px, py, conA, conB}
    __shared__ float4 s2[P_MAX];   // {conC, thr, lopa, 0}
    __shared__ float4 sc[P_MAX];   // {r, g, b, 0}
    __shared__ float4 sback[NPIX]; // back-half partials {r,g,b,T}
    __shared__ int warpcnt[NWARPS];
    __shared__ int warpoff[NWARPS];
    __shared__ int s_count;

    int tid  = threadIdx.x;
    int wid  = tid >> 5;
    int lane = tid & 31;

    float tx0 = (float)(blockIdx.x * TILE_W);
    float tx1 = tx0 + (float)(TILE_W - 1);
    float ty0 = (float)(blockIdx.y * TILE_H);
    float ty1 = ty0 + (float)(TILE_H - 1);

    // ---- Preprocess my gaussian (p == tid) ----
    bool  pred  = false;
    float pix_x = 0.f, pix_y = 0.f, conA = 0.f, conB = 0.f, conC = 0.f;
    float thr = 0.f, lopa = 0.f, depth = 0.f;
    float4 col = make_float4(0.f, 0.f, 0.f, 0.f);

    int p = tid;
    if (p < P) {
        float mx = means3D[3*p+0], my = means3D[3*p+1], mz = means3D[3*p+2];

        float op = 1.0f / (1.0f + __expf(-opacities[p]));

        float sx = __expf(scales[3*p+0]);
        float sy = __expf(scales[3*p+1]);
        float sz = __expf(scales[3*p+2]);

        float4 q4 = ((const float4*)rotations)[p];
        float qr = q4.x, qx = q4.y, qy = q4.z, qz = q4.w;
        float qn = sqrtf(qr*qr + qx*qx + qy*qy + qz*qz);
        qn = fmaxf(qn, 1e-12f);
        float inv = 1.0f / qn;
        qr *= inv; qx *= inv; qy *= inv; qz *= inv;

        float R00 = 1.f - 2.f*(qy*qy + qz*qz), R01 = 2.f*(qx*qy - qr*qz), R02 = 2.f*(qx*qz + qr*qy);
        float R10 = 2.f*(qx*qy + qr*qz), R11 = 1.f - 2.f*(qx*qx + qz*qz), R12 = 2.f*(qy*qz - qr*qx);
        float R20 = 2.f*(qx*qz - qr*qy), R21 = 2.f*(qy*qz + qr*qx), R22 = 1.f - 2.f*(qx*qx + qy*qy);

        float L00 = R00*sx, L01 = R01*sy, L02 = R02*sz;
        float L10 = R10*sx, L11 = R11*sy, L12 = R12*sz;
        float L20 = R20*sx, L21 = R21*sy, L22 = R22*sz;
        float M00 = L00*L00 + L01*L01 + L02*L02;
        float M01 = L00*L10 + L01*L11 + L02*L12;
        float M02 = L00*L20 + L01*L21 + L02*L22;
        float M11 = L10*L10 + L11*L11 + L12*L12;
        float M12 = L10*L20 + L11*L21 + L12*L22;
        float M22 = L20*L20 + L21*L21 + L22*L22;

        float tx = viewm[0]*mx + viewm[1]*my + viewm[2] *mz + viewm[3];
        float ty = viewm[4]*mx + viewm[5]*my + viewm[6] *mz + viewm[7];
        float tz = viewm[8]*mx + viewm[9]*my + viewm[10]*mz + viewm[11];

        bool valid = tz > NEARP;
        float tzc = valid ? tz : 1.0f;

        float limx = 1.3f * TANFOVX, limy = 1.3f * TANFOVY;
        float txz = fminf(fmaxf(tx / tzc, -limx), limx) * tzc;
        float tyz = fminf(fmaxf(ty / tzc, -limy), limy) * tzc;

        float fx = (float)PW / (2.0f * TANFOVX);
        float fy = (float)PH / (2.0f * TANFOVY);
        float itz  = 1.0f / tzc;
        float itz2 = itz * itz;
        float J00 = fx * itz,  J02 = -fx * txz * itz2;
        float J11 = fy * itz,  J12 = -fy * tyz * itz2;

        float u0 = J00*viewm[0] + J02*viewm[8];
        float u1 = J00*viewm[1] + J02*viewm[9];
        float u2 = J00*viewm[2] + J02*viewm[10];
        float v0 = J11*viewm[4] + J12*viewm[8];
        float v1 = J11*viewm[5] + J12*viewm[9];
        float v2 = J11*viewm[6] + J12*viewm[10];

        float Mu0 = M00*u0 + M01*u1 + M02*u2;
        float Mu1 = M01*u0 + M11*u1 + M12*u2;
        float Mu2 = M02*u0 + M12*u1 + M22*u2;
        float Mv0 = M00*v0 + M01*v1 + M02*v2;
        float Mv1 = M01*v0 + M11*v1 + M12*v2;
        float Mv2 = M02*v0 + M12*v1 + M22*v2;

        float c00 = u0*Mu0 + u1*Mu1 + u2*Mu2 + COV_BLUR;
        float c01 = u0*Mv0 + u1*Mv1 + u2*Mv2;
        float c11 = v0*Mv0 + v1*Mv1 + v2*Mv2 + COV_BLUR;

        float det = c00*c11 - c01*c01;
        det = (det == 0.0f) ? 1.0f : det;
        float idet = 1.0f / det;
        conA = c11 * idet;
        conB = -c01 * idet;
        conC = c00 * idet;

        float ph0 = projm[0] *mx + projm[1] *my + projm[2] *mz + projm[3];
        float ph1 = projm[4] *mx + projm[5] *my + projm[6] *mz + projm[7];
        float ph3 = projm[12]*mx + projm[13]*my + projm[14]*mz + projm[15];
        float pw  = 1.0f / (ph3 + 1e-7f);
        pix_x = ((ph0 * pw + 1.0f) * (float)PW - 1.0f) * 0.5f;
        pix_y = ((ph1 * pw + 1.0f) * (float)PH - 1.0f) * 0.5f;

        lopa = __logf(op);
        thr  = __logf(ALPHA_MIN) - lopa;   // contribute iff thr <= power <= 0
        depth = tz;

        if (valid && thr <= 0.0f) {
            float tau = -thr;
            float ex = sqrtf(2.0f * tau * c00);
            float ey = sqrtf(2.0f * tau * c11);
            pred = (pix_x - ex <= tx1) && (pix_x + ex >= tx0) &&
                   (pix_y - ey <= ty1) && (pix_y + ey >= ty0);
        }
        if (pred) {
            col = make_float4(colors[3*p+0], colors[3*p+1], colors[3*p+2], 0.0f);
        }
    }

    // ---- Compact survivors (original index order preserved) ----
    unsigned m = __ballot_sync(0xffffffffu, pred);
    if (lane == 0) warpcnt[wid] = __popc(m);
    __syncthreads();
    if (tid == 0) {
        int acc = 0;
        #pragma unroll
        for (int w = 0; w < NWARPS; w++) { warpoff[w] = acc; acc += warpcnt[w]; }
        s_count = acc;
    }
    __syncthreads();

    int pos = 0;
    if (pred) {
        pos = warpoff[wid] + __popc(m & ((1u << lane) - 1u));
        sdep[pos] = depth;
    }
    __syncthreads();
    int count = s_count;

    // ---- Rank-sort survivors by depth (stable via compact index) ----
    if (pred) {
        int rank = 0;
        for (int j = 0; j < count; j++) {
            float dj = sdep[j];
            rank += (dj < depth) || (dj == depth && j < pos);
        }
        s1[rank] = make_float4(pix_x, pix_y, conA, conB);
        s2[rank] = make_float4(conC, thr, lopa, 0.0f);
        sc[rank] = col;
    }
    __syncthreads();

    // ---- Split-list front-to-back blend: 2 threads per pixel ----
    int pix      = tid & (NPIX - 1);
    int half_sel = tid >> 8;            // 0 = front half of list, 1 = back half
    int lx = pix & (TILE_W - 1);
    int ly = pix / TILE_W;
    float fpx = tx0 + (float)lx;
    float fpy = ty0 + (float)ly;

    int halfc = (count + 1) >> 1;
    int i0 = half_sel ? halfc : 0;
    int i1 = half_sel ? count : halfc;

    float T = 1.0f, cr = 0.0f, cg = 0.0f, cb = 0.0f;

    #pragma unroll 4
    for (int i = i0; i < i1; i++) {
        float4 a = s1[i];                 // px, py, A, B
        float dx = a.x - fpx;
        float dy = a.y - fpy;
        float4 b = s2[i];                 // C, thr, lopa
        float power = -0.5f * (a.z * dx * dx + b.x * dy * dy) - a.w * dx * dy;
        if (power > 0.0f || power < b.y) continue;
        float alpha = fminf(ALPHA_MAX, __expf(power + b.z));
        float4 c = sc[i];
        float w = alpha * T;
        cr += w * c.x;
        cg += w * c.y;
        cb += w * c.z;
        T *= (1.0f - alpha);
        if (T < 1e-4f) break;            // residual weight <= 1e-4 (within tol)
    }

    if (half_sel) {
        sback[pix] = make_float4(cr, cg, cb, T);
    }
    __syncthreads();

    if (!half_sel) {
        float4 bk = sback[pix];
        cr += T * bk.x;
        cg += T * bk.y;
        cb += T * bk.z;
        T  *= bk.w;

        float b0 = bg[0], b1 = bg[1], b2 = bg[2];
        int x = blockIdx.x * TILE_W + lx;
        int y = blockIdx.y * TILE_H + ly;
        int o = (y * PW + x) * 3;
        out[o + 0] = cr + T * b0;
        out[o + 1] = cg + T * b1;
        out[o + 2] = cb + T * b2;
    }
}

// ---------------------------------------------------------------------------
extern "C" void kernel_launch(void* const* d_in, const int* in_sizes, int n_in,
                              void* d_out, int out_size)
{
    const float* means3D   = (const float*)d_in[0];
    const float* opacities = (const float*)d_in[1];
    const float* scales    = (const float*)d_in[2];
    const float* rotations = (const float*)d_in[3];
    const float* colors    = (const float*)d_in[4];
    const float* viewm     = (const float*)d_in[5];
    const float* projm     = (const float*)d_in[6];
    // d_in[7] = campos (unused), d_in[8] = bg
    const float* bg        = (const float*)d_in[8];
    float* out = (float*)d_out;

    int P = in_sizes[0] / 3;
    if (P > P_MAX) P = P_MAX;

    dim3 grid(PW / TILE_W, PH / TILE_H);   // 16 x 16 = 256 blocks
    gs_fused<<<grid, NTHREADS>>>(means3D, opacities, scales, rotations, colors,
                                 viewm, projm, bg, out, P);
}